// round 1
// baseline (speedup 1.0000x reference)
#include <cuda_runtime.h>

// PIF integrate-and-fire, closed form:
//   s = clamp(floor(x + 0.5f), 0, 8)
// Derivation: v0 = x + 0.5; step t fires iff v0 - t >= 1 (repeated -1.0f is
// exact in fp32), so spike count = #{t in [0,8) : v0 >= t+1}
//                                = clamp(floor(v0), 0, 8).
// Pure streaming kernel: 205.5 MB in + 205.5 MB out, HBM-bound.

__global__ void __launch_bounds__(256)
pif_kernel(const float4* __restrict__ x, float4* __restrict__ out, int n4) {
    int i = blockIdx.x * blockDim.x + threadIdx.x;
    if (i < n4) {
        float4 v = x[i];
        float4 r;
        r.x = fminf(8.0f, fmaxf(0.0f, floorf(v.x + 0.5f)));
        r.y = fminf(8.0f, fmaxf(0.0f, floorf(v.y + 0.5f)));
        r.z = fminf(8.0f, fmaxf(0.0f, floorf(v.z + 0.5f)));
        r.w = fminf(8.0f, fmaxf(0.0f, floorf(v.w + 0.5f)));
        out[i] = r;
    }
}

// Tail kernel in case out_size % 4 != 0 (not expected here: 51380224 % 4 == 0,
// but keep launch robust).
__global__ void pif_tail_kernel(const float* __restrict__ x, float* __restrict__ out,
                                int start, int n) {
    int i = start + blockIdx.x * blockDim.x + threadIdx.x;
    if (i < n) {
        out[i] = fminf(8.0f, fmaxf(0.0f, floorf(x[i] + 0.5f)));
    }
}

extern "C" void kernel_launch(void* const* d_in, const int* in_sizes, int n_in,
                              void* d_out, int out_size) {
    const float* x = (const float*)d_in[0];
    float* out = (float*)d_out;
    int n = out_size;

    int n4 = n / 4;
    if (n4 > 0) {
        int threads = 256;
        int blocks = (n4 + threads - 1) / threads;
        pif_kernel<<<blocks, threads>>>((const float4*)x, (float4*)out, n4);
    }
    int rem = n - n4 * 4;
    if (rem > 0) {
        pif_tail_kernel<<<1, 256>>>(x, out, n4 * 4, n);
    }
}

// round 2
// speedup vs baseline: 1.0313x; 1.0313x over previous
#include <cuda_runtime.h>

// PIF integrate-and-fire, closed form: s = clamp(floor(x + 0.5f), 0, 8).
// Pure HBM stream: 205.5 MB in + 205.5 MB out.
//
// R2 changes vs R1:
//  - 4 independent float4 loads per thread, front-batched (MLP_p1=4) to keep
//    the L1tex queue full and ride the DRAM latency/MLP curve.
//  - __ldcs/__stcs streaming hints: zero reuse, evict-first keeps L2 clean.
//  - 4x fewer blocks (12544) -> fewer wave transitions.

#define VPT 4  // float4s per thread

__global__ void __launch_bounds__(256)
pif_kernel(const float4* __restrict__ x, float4* __restrict__ out, int n4) {
    int base = blockIdx.x * (256 * VPT) + threadIdx.x;

    float4 v[VPT];
    bool ok[VPT];
#pragma unroll
    for (int k = 0; k < VPT; k++) {
        int i = base + k * 256;
        ok[k] = i < n4;
        if (ok[k]) v[k] = __ldcs(&x[i]);
    }

#pragma unroll
    for (int k = 0; k < VPT; k++) {
        float4 r;
        r.x = fminf(8.0f, fmaxf(0.0f, floorf(v[k].x + 0.5f)));
        r.y = fminf(8.0f, fmaxf(0.0f, floorf(v[k].y + 0.5f)));
        r.z = fminf(8.0f, fmaxf(0.0f, floorf(v[k].z + 0.5f)));
        r.w = fminf(8.0f, fmaxf(0.0f, floorf(v[k].w + 0.5f)));
        if (ok[k]) __stcs(&out[base + k * 256], r);
    }
}

// Tail for out_size % 4 != 0 (not hit here: 51380224 % 4 == 0).
__global__ void pif_tail_kernel(const float* __restrict__ x, float* __restrict__ out,
                                int start, int n) {
    int i = start + blockIdx.x * blockDim.x + threadIdx.x;
    if (i < n) {
        out[i] = fminf(8.0f, fmaxf(0.0f, floorf(x[i] + 0.5f)));
    }
}

extern "C" void kernel_launch(void* const* d_in, const int* in_sizes, int n_in,
                              void* d_out, int out_size) {
    const float* x = (const float*)d_in[0];
    float* out = (float*)d_out;
    int n = out_size;

    int n4 = n / 4;
    if (n4 > 0) {
        int threads = 256;
        int elems_per_block = threads * VPT;
        int blocks = (n4 + elems_per_block - 1) / elems_per_block;
        pif_kernel<<<blocks, threads>>>((const float4*)x, (float4*)out, n4);
    }
    int rem = n - n4 * 4;
    if (rem > 0) {
        pif_tail_kernel<<<1, 256>>>(x, out, n4 * 4, n);
    }
}